// round 5
// baseline (speedup 1.0000x reference)
#include <cuda_runtime.h>
#include <cuda_bf16.h>
#include <cstdint>

// FlaxHouseholderRoPE: B=2, S=4096, H=32, D=128, R=2, fp32. Single kernel.
// Inputs: q (B,S,H,D), k (B,S,H,D), pos (S), reflectors (H,R,D)  [f32]
// Output: concat(q_out, k_out).
//
// One warp per (b,s,h) vector, processing q AND k. 8 warps/block share the
// same (b,s): threads 0..63 build the 64 (cos,sin) pairs for this s in SMEM.
// Householder: per reflection, one fused butterfly reduces (dot_q, dot_k, |v|^2);
// coef = 2*dot/(|v|^2+eps) — bit-for-bit the reference recurrence.

#define BB 2
#define SS 4096
#define HH 32
#define DD 128
#define NVEC (BB * SS * HH)        // 262144 vectors per tensor

__device__ __forceinline__ float dot4(float4 a, float4 b) {
    return a.x * b.x + a.y * b.y + a.z * b.z + a.w * b.w;
}

__global__ __launch_bounds__(256)
void hh_rope_kernel(const float* __restrict__ q,
                    const float* __restrict__ k,
                    const float* __restrict__ pos,
                    const float* __restrict__ refl,
                    float* __restrict__ out) {
    __shared__ float2 s_cs[64];   // (cos, sin) for pair j of this block's s

    const int tid  = threadIdx.x;
    const int warp = tid >> 5;
    const int lane = tid & 31;
    const int idx  = blockIdx.x * 8 + warp;          // (b*S+s)*H + h
    const int h    = idx & (HH - 1);
    const int s    = (idx >> 5) & (SS - 1);          // same for all 8 warps

    // ---- per-block RoPE table: 64 sincos pairs into SMEM ----
    if (tid < 64) {
        const float LOG2_BASE = 13.287712379549449f;   // log2(10000)
        const float p  = pos[s];
        const float f  = exp2f(-(float)(2 * tid) * (1.0f / 128.0f) * LOG2_BASE);
        float sn, cn;
        sincosf(p * f, &sn, &cn);
        s_cs[tid] = make_float2(cn, sn);
    }
    __syncthreads();

    const size_t off = (size_t)idx * 32 + lane;

    // ---- streamed loads (coalesced LDG.128, evict-first) ----
    float4 xq = __ldcs(reinterpret_cast<const float4*>(q) + off);
    float4 xk = __ldcs(reinterpret_cast<const float4*>(k) + off);

    // ---- two sequential Householder reflections, fused 3-value butterfly ----
    #pragma unroll
    for (int r = 0; r < 2; ++r) {
        const float4 v = reinterpret_cast<const float4*>(refl)[(h * 2 + r) * 32 + lane];
        float dq = dot4(xq, v);
        float dk = dot4(xk, v);
        float sq = dot4(v, v);
        #pragma unroll
        for (int o = 16; o; o >>= 1) {
            dq += __shfl_xor_sync(0xffffffffu, dq, o);
            dk += __shfl_xor_sync(0xffffffffu, dk, o);
            sq += __shfl_xor_sync(0xffffffffu, sq, o);
        }
        const float inv = __frcp_rn(sq + 1e-6f);
        const float cq = 2.0f * dq * inv;
        const float ck = 2.0f * dk * inv;
        xq.x -= cq * v.x;  xq.y -= cq * v.y;  xq.z -= cq * v.z;  xq.w -= cq * v.w;
        xk.x -= ck * v.x;  xk.y -= ck * v.y;  xk.z -= ck * v.z;  xk.w -= ck * v.w;
    }

    // ---- RoPE from SMEM table (conflict-free LDS.128) ----
    const float4 cs = reinterpret_cast<const float4*>(s_cs)[lane];  // (c0,s0,c1,s1)

    float4 oq, ok;
    oq.x = xq.x * cs.x - xq.y * cs.y;
    oq.y = xq.x * cs.y + xq.y * cs.x;
    oq.z = xq.z * cs.z - xq.w * cs.w;
    oq.w = xq.z * cs.w + xq.w * cs.z;
    ok.x = xk.x * cs.x - xk.y * cs.y;
    ok.y = xk.x * cs.y + xk.y * cs.x;
    ok.z = xk.z * cs.z - xk.w * cs.w;
    ok.w = xk.z * cs.w + xk.w * cs.z;

    float4* out4 = reinterpret_cast<float4*>(out);
    __stcs(out4 + off, oq);                              // q half
    __stcs(out4 + (size_t)NVEC * 32 + off, ok);          // k half
}

extern "C" void kernel_launch(void* const* d_in, const int* in_sizes, int n_in,
                              void* d_out, int out_size) {
    const float* q    = (const float*)d_in[0];
    const float* k    = (const float*)d_in[1];
    const float* pos  = (const float*)d_in[2];
    const float* refl = (const float*)d_in[3];
    float* out = (float*)d_out;

    // one warp per (b,s,h): 262144 warps, 8 per block -> 32768 blocks
    hh_rope_kernel<<<NVEC / 8, 256>>>(q, k, pos, refl, out);
}